// round 16
// baseline (speedup 1.0000x reference)
#include <cuda_runtime.h>
#include <cuda_fp16.h>
#include <cstdint>
#include <math.h>

// Problem dims
#define T_STEPS 256
#define B_SZ    32
#define C_SZ    1536
#define M_SZ    1536
#define NBLK    96
#define RTHR    256
#define RING    4

#define N_ELEM_CORE (T_STEPS * B_SZ * C_SZ)   // 12,582,912
#define N_LANES (B_SZ * M_SZ)                 // 49152

// ---------------- device scratch (static globals: no allocations) -------------
__device__ float g_v[C_SZ];
__device__ float g_t[C_SZ];
__device__ float g_pre[N_ELEM_CORE];                       // x@Wx^T + b
__device__ __align__(16) __half g_Ws16[C_SZ * C_SZ];       // fp16 scaled W_h
__device__ __align__(16) __half g_Wx16[C_SZ * C_SZ];       // fp16 W_x
__device__ __align__(16) __half g_X16[N_ELEM_CORE];        // fp16 x_core
__device__ __align__(16) __half g_h16[RING][B_SZ * C_SZ];  // hidden ring
__device__ unsigned g_flag[NBLK];                          // per-block step count
__device__ unsigned g_bar2;                                // barrier (prep)

// ---------------- threefry2x32 (exact JAX partitionable PRNG) ------------------
__device__ __forceinline__ uint32_t rotl32(uint32_t x, int r) {
    return (x << r) | (x >> (32 - r));
}

__device__ __forceinline__ void threefry2x32(uint32_t& x0, uint32_t& x1) {
    const uint32_t k0 = 0u, k1 = 42u;
    const uint32_t k2 = k0 ^ k1 ^ 0x1BD11BDAu;
    const uint32_t ks[3] = {k0, k1, k2};
    const int R0[4] = {13, 15, 26, 6};
    const int R1[4] = {17, 29, 16, 24};
    x0 += ks[0];
    x1 += ks[1];
#pragma unroll
    for (int i = 0; i < 5; i++) {
        const int* r = (i & 1) ? R1 : R0;
#pragma unroll
        for (int j = 0; j < 4; j++) {
            x0 += x1;
            x1 = rotl32(x1, r[j]);
            x1 ^= x0;
        }
        x0 += ks[(i + 1) % 3];
        x1 += ks[(i + 2) % 3] + (uint32_t)(i + 1);
    }
}

__device__ __forceinline__ float bits_to_normal(uint32_t bits) {
    float f = __uint_as_float((bits >> 9) | 0x3f800000u) - 1.0f;  // [0,1)
    const float lo = __uint_as_float(0xBF7FFFFFu);                // nextafter(-1,0)
    float val = __fadd_rn(__fmul_rn(f, 2.0f), lo);
    val = fmaxf(lo, val);
    return 1.41421354f * erfinvf(val);
}

// ---------------- small helpers -------------------------------------------------
__global__ void k_reset_bar() {
    int i = threadIdx.x;
    if (i == 0) g_bar2 = 0u;
    if (i < NBLK) g_flag[i] = 0u;
}

__device__ __forceinline__ float block_sum(float v, float* red2) {
    const int tid = threadIdx.x;
    __syncthreads();
    red2[tid] = v;
    __syncthreads();
    for (int o = 128; o > 0; o >>= 1) {
        if (tid < o) red2[tid] += red2[tid + o];
        __syncthreads();
    }
    return red2[0];
}

__device__ __forceinline__ void gbar2(int phase) {
    __syncthreads();
    if (threadIdx.x == 0) {
        __threadfence();
        atomicAdd(&g_bar2, 1u);
        const unsigned tgt = (unsigned)(phase * NBLK);
        unsigned v;
        do {
            asm volatile("ld.acquire.gpu.u32 %0, [%1];" : "=r"(v) : "l"(&g_bar2));
        } while (v < tgt);
    }
    __syncthreads();
}

__device__ __forceinline__ unsigned ld_acq(const unsigned* p) {
    unsigned v;
    asm volatile("ld.acquire.gpu.u32 %0, [%1];" : "=r"(v) : "l"(p));
    return v;
}

__device__ __forceinline__ float tanh_fast(float x) {
    float r;
    asm("tanh.approx.f32 %0, %1;" : "=f"(r) : "f"(x));
    return r;
}

// ---------------- fused prep kernel ---------------------------------------------
__global__ void __launch_bounds__(256, 1)
k_prep(const float* __restrict__ Wh, const float* __restrict__ Wx,
       const float* __restrict__ X, const float* __restrict__ h0) {
    __shared__ float usm[C_SZ];
    __shared__ float xsm[C_SZ];
    __shared__ float red2[256];
    __shared__ float sbuf[16][17];

    const int tid = threadIdx.x;
    const int blk = blockIdx.x;
    int phase = 0;

    // P0: generate u (partitionable threefry), normalize by /nrm
    {
        float ss = 0.f;
        for (int i = tid; i < C_SZ; i += 256) {
            uint32_t x0 = 0u, x1 = (uint32_t)i;
            threefry2x32(x0, x1);
            float n = bits_to_normal(x0 ^ x1);
            usm[i] = n;
            ss += n * n;
        }
        float s2 = block_sum(ss, red2);
        float nrm = sqrtf(s2);
        __syncthreads();
        for (int i = tid; i < C_SZ; i += 256) usm[i] = usm[i] / nrm;
        __syncthreads();
    }

    // 3 power iterations
    for (int it = 0; it < 3; it++) {
        {
            const int j0 = blk * 16;
            const int c = tid & 15, r = tid >> 4;
            float acc = 0.f;
            for (int i = r; i < C_SZ; i += 16)
                acc = fmaf(Wh[(size_t)i * C_SZ + j0 + c], usm[i], acc);
            sbuf[r][c] = acc;
            __syncthreads();
            if (r == 0) {
                float t = 0.f;
#pragma unroll
                for (int q = 0; q < 16; q++) t += sbuf[q][c];
                g_v[j0 + c] = t;
            }
        }
        gbar2(++phase);

        {
            float p = 0.f;
            for (int i = tid; i < C_SZ; i += 256) {
                float x = g_v[i];
                xsm[i] = x;
                p += x * x;
            }
            float s2 = block_sum(p, red2);
            float s_v = 1.0f / (sqrtf(s2) + 1e-8f);
            __syncthreads();
            const int i0 = blk * 16;
            const int r2 = tid >> 4, c = tid & 15;
            float acc = 0.f;
            for (int j = c; j < C_SZ; j += 16)
                acc = fmaf(Wh[(size_t)(i0 + r2) * C_SZ + j], xsm[j], acc);
            sbuf[r2][c] = acc;
            __syncthreads();
            if (c == 0) {
                float t = 0.f;
#pragma unroll
                for (int q = 0; q < 16; q++) t += sbuf[r2][q];
                g_t[i0 + r2] = t * s_v;
            }
        }
        gbar2(++phase);

        {
            float p = 0.f;
            for (int i = tid; i < C_SZ; i += 256) {
                float x = g_t[i];
                xsm[i] = x;
                p += x * x;
            }
            float s2 = block_sum(p, red2);
            float inv = 1.0f / (sqrtf(s2) + 1e-8f);
            __syncthreads();
            for (int i = tid; i < C_SZ; i += 256) usm[i] = xsm[i] * inv;
            __syncthreads();
        }
    }

    // final: w = W^T u
    {
        const int j0 = blk * 16;
        const int c = tid & 15, r = tid >> 4;
        float acc = 0.f;
        for (int i = r; i < C_SZ; i += 16)
            acc = fmaf(Wh[(size_t)i * C_SZ + j0 + c], usm[i], acc);
        sbuf[r][c] = acc;
        __syncthreads();
        if (r == 0) {
            float t = 0.f;
#pragma unroll
            for (int q = 0; q < 16; q++) t += sbuf[q][c];
            g_t[j0 + c] = t;
        }
    }
    gbar2(++phase);

    // sigma, scale
    float pd = 0.f, pv = 0.f;
    for (int i = tid; i < C_SZ; i += 256) {
        float wv = g_t[i];
        float vv = g_v[i];
        pd = fmaf(wv, vv, pd);
        pv = fmaf(vv, vv, pv);
    }
    float dot = block_sum(pd, red2);
    float sv2 = block_sum(pv, red2);
    float s_v = 1.0f / (sqrtf(sv2) + 1e-8f);
    float sigma = fabsf(dot * s_v);
    float scale = 0.99f / (sigma + 1e-8f);

    // conversions
    const size_t start = (size_t)blk * 256 + tid;
    const size_t stride = (size_t)NBLK * 256;             // 24576
    const float2* Wh2 = (const float2*)Wh;
    const float2* Wx2 = (const float2*)Wx;
    const float2* X2 = (const float2*)X;
    for (size_t i = start; i < (size_t)C_SZ * C_SZ / 2; i += stride) {
        float2 v = Wh2[i];
        ((__half2*)g_Ws16)[i] = __floats2half2_rn(v.x * scale, v.y * scale);
        float2 u = Wx2[i];
        ((__half2*)g_Wx16)[i] = __floats2half2_rn(u.x, u.y);
    }
    for (size_t i = start; i < (size_t)N_ELEM_CORE / 2; i += stride) {
        float2 v = X2[i];
        ((__half2*)g_X16)[i] = __floats2half2_rn(v.x, v.y);
    }
    {
        // h0: one half2 per thread (24576 total)
        float2 v = ((const float2*)h0)[start];
        ((__half2*)g_h16[0])[start] = __floats2half2_rn(v.x, v.y);
    }
}

// ---------------- mma.sync m16n8k16 fp16 -> fp32 -------------------------------
__device__ __forceinline__ void mma16816(float* d, const uint32_t* a, const uint32_t* b) {
    asm volatile(
        "mma.sync.aligned.m16n8k16.row.col.f32.f16.f16.f32 "
        "{%0,%1,%2,%3},{%4,%5,%6,%7},{%8,%9},{%0,%1,%2,%3};"
        : "+f"(d[0]), "+f"(d[1]), "+f"(d[2]), "+f"(d[3])
        : "r"(a[0]), "r"(a[1]), "r"(a[2]), "r"(a[3]), "r"(b[0]), "r"(b[1]));
}

__device__ __forceinline__ void ldsm4(uint32_t* r, uint32_t saddr) {
    asm volatile("ldmatrix.sync.aligned.m8n8.x4.shared.b16 {%0,%1,%2,%3}, [%4];"
                 : "=r"(r[0]), "=r"(r[1]), "=r"(r[2]), "=r"(r[3]) : "r"(saddr));
}

// ---------------- phase-1 GEMM: pre = X @ Wx^T + b ------------------------------
// 128x128 block tile, 512 threads (16 warps, 32x32 warp tiles) for HMMA-pipe
// saturation. Accumulation order per output unchanged (bitwise-identical pre).
__global__ void __launch_bounds__(512) k_gemm16(const float* __restrict__ bc) {
    __shared__ __half As[128][72];
    __shared__ __half Bs[128][72];
    const int bm = blockIdx.y * 128;
    const int bn = blockIdx.x * 128;
    const int tid = threadIdx.x;
    const int w = tid >> 5;
    const int lane = tid & 31;
    const int wm = w >> 2, wn = w & 3;      // 4x4 warp grid, 32x32 each
    const int g = lane >> 2, tg = lane & 3;

    const __half* X = g_X16;
    const __half* Wx = g_Wx16;

    float acc[2][4][4];
#pragma unroll
    for (int i = 0; i < 2; i++)
#pragma unroll
        for (int j = 0; j < 4; j++)
#pragma unroll
            for (int q = 0; q < 4; q++) acc[i][j][q] = 0.f;

    for (int k0 = 0; k0 < C_SZ; k0 += 64) {
#pragma unroll
        for (int it = 0; it < 2; it++) {
            int i = tid + it * 512;        // 0..1023
            int r = i >> 3;                // 0..127
            int c = (i & 7) * 8;
            *(float4*)&As[r][c] = *(const float4*)&X[(size_t)(bm + r) * C_SZ + k0 + c];
            *(float4*)&Bs[r][c] = *(const float4*)&Wx[(size_t)(bn + r) * C_SZ + k0 + c];
        }
        __syncthreads();
#pragma unroll
        for (int kt = 0; kt < 4; kt++) {
            int k = kt * 16;
            uint32_t a[2][4], b[4][2];
#pragma unroll
            for (int mi = 0; mi < 2; mi++) {
                int r0 = wm * 32 + mi * 16 + g;
                a[mi][0] = *(const uint32_t*)&As[r0][k + 2 * tg];
                a[mi][1] = *(const uint32_t*)&As[r0 + 8][k + 2 * tg];
                a[mi][2] = *(const uint32_t*)&As[r0][k + 2 * tg + 8];
                a[mi][3] = *(const uint32_t*)&As[r0 + 8][k + 2 * tg + 8];
            }
#pragma unroll
            for (int ni = 0; ni < 4; ni++) {
                int r0 = wn * 32 + ni * 8 + g;
                b[ni][0] = *(const uint32_t*)&Bs[r0][k + 2 * tg];
                b[ni][1] = *(const uint32_t*)&Bs[r0][k + 2 * tg + 8];
            }
#pragma unroll
            for (int mi = 0; mi < 2; mi++)
#pragma unroll
                for (int ni = 0; ni < 4; ni++)
                    mma16816(acc[mi][ni], a[mi], b[ni]);
        }
        __syncthreads();
    }

#pragma unroll
    for (int mi = 0; mi < 2; mi++) {
        int row = bm + wm * 32 + mi * 16 + g;
#pragma unroll
        for (int ni = 0; ni < 4; ni++) {
            int col = bn + wn * 32 + ni * 8 + 2 * tg;
            float b0 = bc[col], b1 = bc[col + 1];
            float2 o0 = make_float2(acc[mi][ni][0] + b0, acc[mi][ni][1] + b1);
            float2 o1 = make_float2(acc[mi][ni][2] + b0, acc[mi][ni][3] + b1);
            *(float2*)&g_pre[(size_t)row * C_SZ + col] = o0;
            *(float2*)&g_pre[(size_t)(row + 8) * C_SZ + col] = o1;
        }
    }
}

// ---------------- persistent recurrence kernel (96 blocks x 256 threads) -------
// Per-block monotone step-flag, single st.release per block per step.
// Warp w polls only its 12 producers (blocks 12w..12w+11); back-pressure and
// next-step pre/z prefetch run in the epilogue slack.
#define SH 1544
#define SMEM_R (32 * SH * 2 + 2 * 8 * 512 * 4)   // h tile + double reduction buf

__global__ void __launch_bounds__(RTHR, 1)
k_recurrent(const float* __restrict__ zc,
            float* __restrict__ out_core,
            float* __restrict__ h_core_f,
            const float* __restrict__ xm, const float* __restrict__ zm,
            const float* __restrict__ h0m, const float* __restrict__ am,
            float* __restrict__ out_mem, float* __restrict__ h_mem_f) {
    extern __shared__ __align__(16) char smem[];
    __half* hsm = (__half*)smem;                        // [32][SH]
    float* red = (float*)(smem + 32 * SH * 2);          // [2][8][512]

    const int n0 = blockIdx.x * 16;
    const int tid = threadIdx.x;
    const int w = tid >> 5;
    const int lane = tid & 31;
    const int g = lane >> 2, tg = lane & 3;
    const int kbase = w * 192;

    // ---- W fragments once into registers (48 regs) ----
    uint32_t bf[12][2][2];
#pragma unroll
    for (int kt = 0; kt < 12; kt++) {
        int k0 = kbase + kt * 16 + 2 * tg;
#pragma unroll
        for (int ni = 0; ni < 2; ni++) {
            const __half* wr = g_Ws16 + (size_t)(n0 + ni * 8 + g) * C_SZ;
            bf[kt][ni][0] = *(const uint32_t*)(wr + k0);
            bf[kt][ni][1] = *(const uint32_t*)(wr + k0 + 8);
        }
    }

    // ldmatrix lane address bases
    const uint32_t hsm_s = (uint32_t)__cvta_generic_to_shared(hsm);
    const int lrow = lane & 15;
    const int lcol = (lane >> 4) * 8;
    const uint32_t a_base0 = hsm_s + (uint32_t)((lrow * SH + lcol + kbase) * 2);
    const uint32_t a_base1 = a_base0 + (uint32_t)(16 * SH * 2);

    // output pair mapping
    const int o0 = 2 * tid;              // 0..510
    const int ob = o0 >> 4;              // batch row
    const int oc = n0 + (o0 & 15);       // global col

    // producer flag index for this warp's poll (12 producers)
    const int prod = 12 * w + (lane % 12);

    // ---- fused mem-scan state (2 lanes per thread) ----
    const int lm0 = blockIdx.x * RTHR + tid;     // 0..24575
    const int lm1 = lm0 + NBLK * RTHR;           // +24576 (same m index)
    const float dec = 1.0f / (1.0f + expf(-am[lm0 % M_SZ]));
    float hm0 = h0m[lm0], hm1 = h0m[lm1];
    float mx0 = xm[lm0], mz0 = zm[lm0];
    float mx1 = xm[lm1], mz1 = zm[lm1];

    // pre/z prefetch for step 0
    float2 pre2 = *(const float2*)&g_pre[(size_t)ob * C_SZ + oc];
    float2 z2 = *(const float2*)&zc[(size_t)ob * C_SZ + oc];

    for (int t = 0; t < T_STEPS; t++) {
        const __half* hb = g_h16[t & (RING - 1)];
        __half* hn = g_h16[(t + 1) & (RING - 1)];
        const size_t base = (size_t)t * B_SZ * C_SZ;
        const size_t oidx = base + (size_t)ob * C_SZ + oc;

        // ---- producer poll: this warp's 12 producers have published step t ----
        {
            const unsigned tgt = (unsigned)t;
            bool ok;
            do {
                unsigned f = ld_acq(&g_flag[prod]);
                ok = __all_sync(0xffffffffu, f >= tgt);
            } while (!ok);
        }

        // ---- stage own K-slice: 32 rows x 192 cols (768 float4) ----
#pragma unroll
        for (int i = 0; i < 24; i++) {
            int idx = i * 32 + lane;          // 0..767
            int r = idx / 24;
            int c = kbase + (idx % 24) * 8;
            float4 v = __ldcg((const float4*)(hb + (size_t)r * C_SZ + c));
            *(float4*)&hsm[r * SH + c] = v;
        }
        __syncwarp();

        float acc[2][2][4];
#pragma unroll
        for (int i = 0; i < 2; i++)
#pragma unroll
            for (int j = 0; j < 2; j++)
#pragma unroll
                for (int q = 0; q < 4; q++) acc[i][j][q] = 0.f;

#pragma unroll
        for (int kt = 0; kt < 12; kt++) {
            const uint32_t koff = (uint32_t)(kt * 32);
            uint32_t a0[4], a1[4];
            ldsm4(a0, a_base0 + koff);
            ldsm4(a1, a_base1 + koff);
#pragma unroll
            for (int ni = 0; ni < 2; ni++) {
                mma16816(acc[0][ni], a0, bf[kt][ni]);
                mma16816(acc[1][ni], a1, bf[kt][ni]);
            }
        }

        // warp partials into parity-selected buffer
        float* rp = red + (t & 1) * (8 * 512);
#pragma unroll
        for (int mi = 0; mi < 2; mi++)
#pragma unroll
            for (int ni = 0; ni < 2; ni++) {
                int r0 = mi * 16 + g;
                int c0 = ni * 8 + 2 * tg;
                *(float2*)&rp[w * 512 + r0 * 16 + c0] =
                    make_float2(acc[mi][ni][0], acc[mi][ni][1]);
                *(float2*)&rp[w * 512 + (r0 + 8) * 16 + c0] =
                    make_float2(acc[mi][ni][2], acc[mi][ni][3]);
            }
        __syncthreads();

        // reduce 8 warp partials, tanh (approx), store h_next
        float s0 = 0.f, s1 = 0.f;
#pragma unroll
        for (int q = 0; q < 8; q++) {
            float2 v = *(const float2*)&rp[q * 512 + o0];
            s0 += v.x;
            s1 += v.y;
        }
        float hv0 = tanh_fast(pre2.x + s0);
        float hv1 = tanh_fast(pre2.y + s1);
        __stcg((__half2*)&hn[ob * C_SZ + oc], __floats2half2_rn(hv0, hv1));
        __syncthreads();   // all block h stores issued before release

        // ---- single release per block: flag[blk] = t+1 ----
        if (tid == 0)
            asm volatile("st.release.gpu.global.u32 [%0], %1;"
                         :: "l"(&g_flag[blockIdx.x]), "r"((unsigned)(t + 1))
                         : "memory");

        // ================= epilogue in pipeline slack =================
        {
            float sl0 = z2.x * (1.0f / (1.0f + __expf(-z2.x)));
            float sl1 = z2.y * (1.0f / (1.0f + __expf(-z2.y)));
            *(float2*)&out_core[oidx] = make_float2(hv0 * sl0, hv1 * sl1);
        }
        if (t == T_STEPS - 1)
            *(float2*)&h_core_f[ob * C_SZ + oc] = make_float2(hv0, hv1);

        // fused mem-branch step (fast sigmoid: ~1e-7 rel err on an output)
        {
            const size_t moff = (size_t)t * N_LANES;
            hm0 = fmaf(dec, hm0, mx0);
            out_mem[moff + lm0] = hm0 * (mz0 * (1.0f / (1.0f + __expf(-mz0))));
            hm1 = fmaf(dec, hm1, mx1);
            out_mem[moff + lm1] = hm1 * (mz1 * (1.0f / (1.0f + __expf(-mz1))));
            if (t + 1 < T_STEPS) {
                const size_t noff = (size_t)(t + 1) * N_LANES;
                mx0 = xm[noff + lm0]; mz0 = zm[noff + lm0];
                mx1 = xm[noff + lm1]; mz1 = zm[noff + lm1];
            }
        }

        // prefetch pre/z for step t+1
        if (t + 1 < T_STEPS) {
            const size_t nidx = (size_t)(t + 1) * B_SZ * C_SZ + (size_t)ob * C_SZ + oc;
            pre2 = *(const float2*)&g_pre[nidx];
            z2 = *(const float2*)&zc[nidx];
        }

        // back-pressure (licenses next step's h write into the 4-deep ring)
        if (t >= 2 && t + 1 < T_STEPS) {
            const unsigned tgt = (unsigned)(t - 1);
            bool ok;
            do {
                unsigned f0 = ld_acq(&g_flag[lane]);
                unsigned f1 = ld_acq(&g_flag[lane + 32]);
                unsigned f2 = ld_acq(&g_flag[lane + 64]);
                ok = __all_sync(0xffffffffu,
                                f0 >= tgt && f1 >= tgt && f2 >= tgt);
            } while (!ok);
        }
    }

    h_mem_f[lm0] = hm0;
    h_mem_f[lm1] = hm1;
}

// ---------------- launch --------------------------------------------------------
extern "C" void kernel_launch(void* const* d_in, const int* in_sizes, int n_in,
                              void* d_out, int out_size) {
    const float* x_core  = (const float*)d_in[0];
    const float* z_core  = (const float*)d_in[1];
    const float* x_mem   = (const float*)d_in[2];
    const float* z_mem   = (const float*)d_in[3];
    const float* h0_core = (const float*)d_in[4];
    const float* h0_mem  = (const float*)d_in[5];
    const float* W_x     = (const float*)d_in[6];
    const float* W_h     = (const float*)d_in[7];
    const float* b_core  = (const float*)d_in[8];
    const float* a_mem   = (const float*)d_in[9];

    float* out       = (float*)d_out;
    float* out_core  = out;
    float* out_mem   = out + (size_t)T_STEPS * B_SZ * C_SZ;
    float* h_core_f  = out_mem + (size_t)T_STEPS * B_SZ * M_SZ;
    float* h_mem_f   = h_core_f + (size_t)B_SZ * C_SZ;

    cudaFuncSetAttribute(k_recurrent, cudaFuncAttributeMaxDynamicSharedMemorySize,
                         SMEM_R);

    // reset flags + prep barrier
    k_reset_bar<<<1, 128>>>();

    // fused spectral norm + fp16 conversions + h0 init
    k_prep<<<NBLK, 256>>>(W_h, W_x, x_core, h0_core);

    // pre = x_core @ W_x^T + b_core (tensor cores, 128x128 tiles, 512 threads)
    {
        dim3 grid(C_SZ / 128, (T_STEPS * B_SZ) / 128);  // (12, 64)
        k_gemm16<<<grid, 512>>>(b_core);
    }

    // persistent recurrence over all 256 steps (mem scan fused in)
    k_recurrent<<<NBLK, RTHR, SMEM_R>>>(z_core, out_core, h_core_f,
                                        x_mem, z_mem, h0_mem, a_mem,
                                        out_mem, h_mem_f);
}

// round 17
// speedup vs baseline: 1.1322x; 1.1322x over previous
#include <cuda_runtime.h>
#include <cuda_fp16.h>
#include <cstdint>
#include <math.h>

// Problem dims
#define T_STEPS 256
#define B_SZ    32
#define C_SZ    1536
#define M_SZ    1536
#define NBLK    96          // recurrence blocks
#define GBLK    52          // fused GEMM blocks
#define TOTBLK  (NBLK + GBLK)
#define RTHR    256
#define RING    4
#define NTILES  768         // 64 m-tiles x 12 n-tiles

#define N_ELEM_CORE (T_STEPS * B_SZ * C_SZ)   // 12,582,912
#define N_LANES (B_SZ * M_SZ)                 // 49152

// ---------------- device scratch (static globals: no allocations) -------------
__device__ float g_v[C_SZ];
__device__ float g_t[C_SZ];
__device__ float g_pre[N_ELEM_CORE];                       // x@Wx^T + b
__device__ __align__(16) __half g_Ws16[C_SZ * C_SZ];       // fp16 scaled W_h
__device__ __align__(16) __half g_Wx16[C_SZ * C_SZ];       // fp16 W_x
__device__ __align__(16) __half g_X16[N_ELEM_CORE];        // fp16 x_core
__device__ __align__(16) __half g_h16[RING][B_SZ * C_SZ];  // hidden ring
__device__ unsigned g_flag[NBLK];                          // per-block step count
__device__ unsigned g_pre_done[64];                        // per m-group tiles done
__device__ unsigned g_bar2;                                // barrier (prep)

// ---------------- threefry2x32 (exact JAX partitionable PRNG) ------------------
__device__ __forceinline__ uint32_t rotl32(uint32_t x, int r) {
    return (x << r) | (x >> (32 - r));
}

__device__ __forceinline__ void threefry2x32(uint32_t& x0, uint32_t& x1) {
    const uint32_t k0 = 0u, k1 = 42u;
    const uint32_t k2 = k0 ^ k1 ^ 0x1BD11BDAu;
    const uint32_t ks[3] = {k0, k1, k2};
    const int R0[4] = {13, 15, 26, 6};
    const int R1[4] = {17, 29, 16, 24};
    x0 += ks[0];
    x1 += ks[1];
#pragma unroll
    for (int i = 0; i < 5; i++) {
        const int* r = (i & 1) ? R1 : R0;
#pragma unroll
        for (int j = 0; j < 4; j++) {
            x0 += x1;
            x1 = rotl32(x1, r[j]);
            x1 ^= x0;
        }
        x0 += ks[(i + 1) % 3];
        x1 += ks[(i + 2) % 3] + (uint32_t)(i + 1);
    }
}

__device__ __forceinline__ float bits_to_normal(uint32_t bits) {
    float f = __uint_as_float((bits >> 9) | 0x3f800000u) - 1.0f;  // [0,1)
    const float lo = __uint_as_float(0xBF7FFFFFu);                // nextafter(-1,0)
    float val = __fadd_rn(__fmul_rn(f, 2.0f), lo);
    val = fmaxf(lo, val);
    return 1.41421354f * erfinvf(val);
}

// ---------------- small helpers -------------------------------------------------
__global__ void k_reset_bar() {
    int i = threadIdx.x;
    if (i == 0) g_bar2 = 0u;
    if (i < NBLK) g_flag[i] = 0u;
    if (i < 64) g_pre_done[i] = 0u;
}

__device__ __forceinline__ float block_sum(float v, float* red2) {
    const int tid = threadIdx.x;
    __syncthreads();
    red2[tid] = v;
    __syncthreads();
    for (int o = 128; o > 0; o >>= 1) {
        if (tid < o) red2[tid] += red2[tid + o];
        __syncthreads();
    }
    return red2[0];
}

__device__ __forceinline__ void gbar2(int phase) {
    __syncthreads();
    if (threadIdx.x == 0) {
        __threadfence();
        atomicAdd(&g_bar2, 1u);
        const unsigned tgt = (unsigned)(phase * NBLK);
        unsigned v;
        do {
            asm volatile("ld.acquire.gpu.u32 %0, [%1];" : "=r"(v) : "l"(&g_bar2));
        } while (v < tgt);
    }
    __syncthreads();
}

__device__ __forceinline__ unsigned ld_acq(const unsigned* p) {
    unsigned v;
    asm volatile("ld.acquire.gpu.u32 %0, [%1];" : "=r"(v) : "l"(p));
    return v;
}

__device__ __forceinline__ float tanh_fast(float x) {
    float r;
    asm("tanh.approx.f32 %0, %1;" : "=f"(r) : "f"(x));
    return r;
}

// ---------------- fused prep kernel ---------------------------------------------
__global__ void __launch_bounds__(256, 1)
k_prep(const float* __restrict__ Wh, const float* __restrict__ Wx,
       const float* __restrict__ X, const float* __restrict__ h0) {
    __shared__ float usm[C_SZ];
    __shared__ float xsm[C_SZ];
    __shared__ float red2[256];
    __shared__ float sbuf[16][17];

    const int tid = threadIdx.x;
    const int blk = blockIdx.x;
    int phase = 0;

    // P0: generate u (partitionable threefry), normalize by /nrm
    {
        float ss = 0.f;
        for (int i = tid; i < C_SZ; i += 256) {
            uint32_t x0 = 0u, x1 = (uint32_t)i;
            threefry2x32(x0, x1);
            float n = bits_to_normal(x0 ^ x1);
            usm[i] = n;
            ss += n * n;
        }
        float s2 = block_sum(ss, red2);
        float nrm = sqrtf(s2);
        __syncthreads();
        for (int i = tid; i < C_SZ; i += 256) usm[i] = usm[i] / nrm;
        __syncthreads();
    }

    // 3 power iterations
    for (int it = 0; it < 3; it++) {
        {
            const int j0 = blk * 16;
            const int c = tid & 15, r = tid >> 4;
            float acc = 0.f;
            for (int i = r; i < C_SZ; i += 16)
                acc = fmaf(Wh[(size_t)i * C_SZ + j0 + c], usm[i], acc);
            sbuf[r][c] = acc;
            __syncthreads();
            if (r == 0) {
                float t = 0.f;
#pragma unroll
                for (int q = 0; q < 16; q++) t += sbuf[q][c];
                g_v[j0 + c] = t;
            }
        }
        gbar2(++phase);

        {
            float p = 0.f;
            for (int i = tid; i < C_SZ; i += 256) {
                float x = g_v[i];
                xsm[i] = x;
                p += x * x;
            }
            float s2 = block_sum(p, red2);
            float s_v = 1.0f / (sqrtf(s2) + 1e-8f);
            __syncthreads();
            const int i0 = blk * 16;
            const int r2 = tid >> 4, c = tid & 15;
            float acc = 0.f;
            for (int j = c; j < C_SZ; j += 16)
                acc = fmaf(Wh[(size_t)(i0 + r2) * C_SZ + j], xsm[j], acc);
            sbuf[r2][c] = acc;
            __syncthreads();
            if (c == 0) {
                float t = 0.f;
#pragma unroll
                for (int q = 0; q < 16; q++) t += sbuf[r2][q];
                g_t[i0 + r2] = t * s_v;
            }
        }
        gbar2(++phase);

        {
            float p = 0.f;
            for (int i = tid; i < C_SZ; i += 256) {
                float x = g_t[i];
                xsm[i] = x;
                p += x * x;
            }
            float s2 = block_sum(p, red2);
            float inv = 1.0f / (sqrtf(s2) + 1e-8f);
            __syncthreads();
            for (int i = tid; i < C_SZ; i += 256) usm[i] = xsm[i] * inv;
            __syncthreads();
        }
    }

    // final: w = W^T u
    {
        const int j0 = blk * 16;
        const int c = tid & 15, r = tid >> 4;
        float acc = 0.f;
        for (int i = r; i < C_SZ; i += 16)
            acc = fmaf(Wh[(size_t)i * C_SZ + j0 + c], usm[i], acc);
        sbuf[r][c] = acc;
        __syncthreads();
        if (r == 0) {
            float t = 0.f;
#pragma unroll
            for (int q = 0; q < 16; q++) t += sbuf[q][c];
            g_t[j0 + c] = t;
        }
    }
    gbar2(++phase);

    // sigma, scale
    float pd = 0.f, pv = 0.f;
    for (int i = tid; i < C_SZ; i += 256) {
        float wv = g_t[i];
        float vv = g_v[i];
        pd = fmaf(wv, vv, pd);
        pv = fmaf(vv, vv, pv);
    }
    float dot = block_sum(pd, red2);
    float sv2 = block_sum(pv, red2);
    float s_v = 1.0f / (sqrtf(sv2) + 1e-8f);
    float sigma = fabsf(dot * s_v);
    float scale = 0.99f / (sigma + 1e-8f);

    // conversions
    const size_t start = (size_t)blk * 256 + tid;
    const size_t stride = (size_t)NBLK * 256;             // 24576
    const float2* Wh2 = (const float2*)Wh;
    const float2* Wx2 = (const float2*)Wx;
    const float2* X2 = (const float2*)X;
    for (size_t i = start; i < (size_t)C_SZ * C_SZ / 2; i += stride) {
        float2 v = Wh2[i];
        ((__half2*)g_Ws16)[i] = __floats2half2_rn(v.x * scale, v.y * scale);
        float2 u = Wx2[i];
        ((__half2*)g_Wx16)[i] = __floats2half2_rn(u.x, u.y);
    }
    for (size_t i = start; i < (size_t)N_ELEM_CORE / 2; i += stride) {
        float2 v = X2[i];
        ((__half2*)g_X16)[i] = __floats2half2_rn(v.x, v.y);
    }
    {
        // h0: one half2 per thread (24576 total)
        float2 v = ((const float2*)h0)[start];
        ((__half2*)g_h16[0])[start] = __floats2half2_rn(v.x, v.y);
    }
}

// ---------------- mma.sync m16n8k16 fp16 -> fp32 -------------------------------
__device__ __forceinline__ void mma16816(float* d, const uint32_t* a, const uint32_t* b) {
    asm volatile(
        "mma.sync.aligned.m16n8k16.row.col.f32.f16.f16.f32 "
        "{%0,%1,%2,%3},{%4,%5,%6,%7},{%8,%9},{%0,%1,%2,%3};"
        : "+f"(d[0]), "+f"(d[1]), "+f"(d[2]), "+f"(d[3])
        : "r"(a[0]), "r"(a[1]), "r"(a[2]), "r"(a[3]), "r"(b[0]), "r"(b[1]));
}

__device__ __forceinline__ void ldsm4(uint32_t* r, uint32_t saddr) {
    asm volatile("ldmatrix.sync.aligned.m8n8.x4.shared.b16 {%0,%1,%2,%3}, [%4];"
                 : "=r"(r[0]), "=r"(r[1]), "=r"(r[2]), "=r"(r[3]) : "r"(saddr));
}

// ---------------- fused GEMM part (blocks 96..147 of k_main) --------------------
// pre = X @ Wx^T + b, 128x128 tiles, m(time)-major tile order, 256 threads.
// After each tile: fence + syncthreads + release-add on the m-group counter.
__device__ __forceinline__ void gemm_part(int gb, const float* __restrict__ bc) {
    extern __shared__ __align__(16) char smem[];
    __half* As = (__half*)smem;          // [128][72]
    __half* Bs = As + 128 * 72;          // [128][72]

    const int tid = threadIdx.x;
    const int w = tid >> 5;
    const int lane = tid & 31;
    const int wm = w >> 1, wn = w & 1;
    const int g = lane >> 2, tg = lane & 3;

    for (int q = gb; q < NTILES; q += GBLK) {
        const int mt = q / 12, nt = q % 12;
        const int bm = mt * 128, bn = nt * 128;

        float acc[2][8][4];
#pragma unroll
        for (int i = 0; i < 2; i++)
#pragma unroll
            for (int j = 0; j < 8; j++)
#pragma unroll
                for (int p = 0; p < 4; p++) acc[i][j][p] = 0.f;

        for (int k0 = 0; k0 < C_SZ; k0 += 64) {
#pragma unroll
            for (int it = 0; it < 4; it++) {
                int i = tid + it * 256;
                int r = i >> 3;
                int c = (i & 7) * 8;
                *(float4*)&As[r * 72 + c] =
                    *(const float4*)&g_X16[(size_t)(bm + r) * C_SZ + k0 + c];
                *(float4*)&Bs[r * 72 + c] =
                    *(const float4*)&g_Wx16[(size_t)(bn + r) * C_SZ + k0 + c];
            }
            __syncthreads();
#pragma unroll
            for (int kt = 0; kt < 4; kt++) {
                int k = kt * 16;
                uint32_t a[2][4], b[8][2];
#pragma unroll
                for (int mi = 0; mi < 2; mi++) {
                    int r0 = wm * 32 + mi * 16 + g;
                    a[mi][0] = *(const uint32_t*)&As[r0 * 72 + k + 2 * tg];
                    a[mi][1] = *(const uint32_t*)&As[(r0 + 8) * 72 + k + 2 * tg];
                    a[mi][2] = *(const uint32_t*)&As[r0 * 72 + k + 2 * tg + 8];
                    a[mi][3] = *(const uint32_t*)&As[(r0 + 8) * 72 + k + 2 * tg + 8];
                }
#pragma unroll
                for (int ni = 0; ni < 8; ni++) {
                    int r0 = wn * 64 + ni * 8 + g;
                    b[ni][0] = *(const uint32_t*)&Bs[r0 * 72 + k + 2 * tg];
                    b[ni][1] = *(const uint32_t*)&Bs[r0 * 72 + k + 2 * tg + 8];
                }
#pragma unroll
                for (int mi = 0; mi < 2; mi++)
#pragma unroll
                    for (int ni = 0; ni < 8; ni++)
                        mma16816(acc[mi][ni], a[mi], b[ni]);
            }
            __syncthreads();
        }

#pragma unroll
        for (int mi = 0; mi < 2; mi++) {
            int row = bm + wm * 32 + mi * 16 + g;
#pragma unroll
            for (int ni = 0; ni < 8; ni++) {
                int col = bn + wn * 64 + ni * 8 + 2 * tg;
                float b0 = bc[col], b1 = bc[col + 1];
                float2 o0 = make_float2(acc[mi][ni][0] + b0, acc[mi][ni][1] + b1);
                float2 o1 = make_float2(acc[mi][ni][2] + b0, acc[mi][ni][3] + b1);
                *(float2*)&g_pre[(size_t)row * C_SZ + col] = o0;
                *(float2*)&g_pre[(size_t)(row + 8) * C_SZ + col] = o1;
            }
        }

        // publish tile: every thread fences its stores, then one release-add
        __threadfence();
        __syncthreads();
        if (tid == 0)
            asm volatile("red.release.gpu.global.add.u32 [%0], 1;"
                         :: "l"(&g_pre_done[mt]) : "memory");
    }
}

// ---------------- combined persistent kernel (148 blocks x 256 threads) --------
// Blocks 0..95: pipelined recurrence (R14 scheme). Blocks 96..147: fused GEMM.
#define SH 1544
#define SMEM_R (32 * SH * 2 + 2 * 8 * 512 * 4)   // h tile + double reduction buf

__global__ void __launch_bounds__(RTHR, 1)
k_main(const float* __restrict__ zc,
       float* __restrict__ out_core,
       float* __restrict__ h_core_f,
       const float* __restrict__ xm, const float* __restrict__ zm,
       const float* __restrict__ h0m, const float* __restrict__ am,
       float* __restrict__ out_mem, float* __restrict__ h_mem_f,
       const float* __restrict__ bc) {
    if (blockIdx.x >= NBLK) {
        gemm_part(blockIdx.x - NBLK, bc);
        return;
    }

    extern __shared__ __align__(16) char smem[];
    __half* hsm = (__half*)smem;                        // [32][SH]
    float* red = (float*)(smem + 32 * SH * 2);          // [2][8][512]

    const int n0 = blockIdx.x * 16;
    const int tid = threadIdx.x;
    const int w = tid >> 5;
    const int lane = tid & 31;
    const int g = lane >> 2, tg = lane & 3;
    const int kbase = w * 192;

    // ---- W fragments once into registers (48 regs) ----
    uint32_t bf[12][2][2];
#pragma unroll
    for (int kt = 0; kt < 12; kt++) {
        int k0 = kbase + kt * 16 + 2 * tg;
#pragma unroll
        for (int ni = 0; ni < 2; ni++) {
            const __half* wr = g_Ws16 + (size_t)(n0 + ni * 8 + g) * C_SZ;
            bf[kt][ni][0] = *(const uint32_t*)(wr + k0);
            bf[kt][ni][1] = *(const uint32_t*)(wr + k0 + 8);
        }
    }

    // ldmatrix lane address bases
    const uint32_t hsm_s = (uint32_t)__cvta_generic_to_shared(hsm);
    const int lrow = lane & 15;
    const int lcol = (lane >> 4) * 8;
    const uint32_t a_base0 = hsm_s + (uint32_t)((lrow * SH + lcol + kbase) * 2);
    const uint32_t a_base1 = a_base0 + (uint32_t)(16 * SH * 2);

    // output pair mapping
    const int o0 = 2 * tid;              // 0..510
    const int ob = o0 >> 4;              // batch row
    const int oc = n0 + (o0 & 15);       // global col

    // producer flag index for this warp's poll (12 producers)
    const int prod = 12 * w + (lane % 12);

    // ---- fused mem-scan state (2 lanes per thread) ----
    const int lm0 = blockIdx.x * RTHR + tid;     // 0..24575
    const int lm1 = lm0 + NBLK * RTHR;           // +24576 (same m index)
    const float dec = 1.0f / (1.0f + expf(-am[lm0 % M_SZ]));
    float hm0 = h0m[lm0], hm1 = h0m[lm1];
    float mx0 = xm[lm0], mz0 = zm[lm0];
    float mx1 = xm[lm1], mz1 = zm[lm1];

    // wait for pre group 0, then prefetch pre/z for step 0 (pre via L2)
    {
        unsigned d;
        do { d = ld_acq(&g_pre_done[0]); } while (d < 12u);
    }
    float2 pre2 = __ldcg((const float2*)&g_pre[(size_t)ob * C_SZ + oc]);
    float2 z2 = *(const float2*)&zc[(size_t)ob * C_SZ + oc];

    for (int t = 0; t < T_STEPS; t++) {
        const __half* hb = g_h16[t & (RING - 1)];
        __half* hn = g_h16[(t + 1) & (RING - 1)];
        const size_t base = (size_t)t * B_SZ * C_SZ;
        const size_t oidx = base + (size_t)ob * C_SZ + oc;

        // ---- producer poll: this warp's 12 producers have published step t ----
        {
            const unsigned tgt = (unsigned)t;
            bool ok;
            do {
                unsigned f = ld_acq(&g_flag[prod]);
                ok = __all_sync(0xffffffffu, f >= tgt);
            } while (!ok);
        }

        // ---- stage own K-slice: 32 rows x 192 cols (768 float4) ----
#pragma unroll
        for (int i = 0; i < 24; i++) {
            int idx = i * 32 + lane;          // 0..767
            int r = idx / 24;
            int c = kbase + (idx % 24) * 8;
            float4 v = __ldcg((const float4*)(hb + (size_t)r * C_SZ + c));
            *(float4*)&hsm[r * SH + c] = v;
        }
        __syncwarp();

        float acc[2][2][4];
#pragma unroll
        for (int i = 0; i < 2; i++)
#pragma unroll
            for (int j = 0; j < 2; j++)
#pragma unroll
                for (int q = 0; q < 4; q++) acc[i][j][q] = 0.f;

#pragma unroll
        for (int kt = 0; kt < 12; kt++) {
            const uint32_t koff = (uint32_t)(kt * 32);
            uint32_t a0[4], a1[4];
            ldsm4(a0, a_base0 + koff);
            ldsm4(a1, a_base1 + koff);
#pragma unroll
            for (int ni = 0; ni < 2; ni++) {
                mma16816(acc[0][ni], a0, bf[kt][ni]);
                mma16816(acc[1][ni], a1, bf[kt][ni]);
            }
        }

        // warp partials into parity-selected buffer
        float* rp = red + (t & 1) * (8 * 512);
#pragma unroll
        for (int mi = 0; mi < 2; mi++)
#pragma unroll
            for (int ni = 0; ni < 2; ni++) {
                int r0 = mi * 16 + g;
                int c0 = ni * 8 + 2 * tg;
                *(float2*)&rp[w * 512 + r0 * 16 + c0] =
                    make_float2(acc[mi][ni][0], acc[mi][ni][1]);
                *(float2*)&rp[w * 512 + (r0 + 8) * 16 + c0] =
                    make_float2(acc[mi][ni][2], acc[mi][ni][3]);
            }
        __syncthreads();

        // reduce 8 warp partials, tanh (approx), store h_next
        float s0 = 0.f, s1 = 0.f;
#pragma unroll
        for (int q = 0; q < 8; q++) {
            float2 v = *(const float2*)&rp[q * 512 + o0];
            s0 += v.x;
            s1 += v.y;
        }
        float hv0 = tanh_fast(pre2.x + s0);
        float hv1 = tanh_fast(pre2.y + s1);
        __stcg((__half2*)&hn[ob * C_SZ + oc], __floats2half2_rn(hv0, hv1));
        __syncthreads();   // all block h stores issued before release

        // ---- single release per block: flag[blk] = t+1 ----
        if (tid == 0)
            asm volatile("st.release.gpu.global.u32 [%0], %1;"
                         :: "l"(&g_flag[blockIdx.x]), "r"((unsigned)(t + 1))
                         : "memory");

        // ================= epilogue in pipeline slack =================
        {
            float sl0 = z2.x * (1.0f / (1.0f + __expf(-z2.x)));
            float sl1 = z2.y * (1.0f / (1.0f + __expf(-z2.y)));
            *(float2*)&out_core[oidx] = make_float2(hv0 * sl0, hv1 * sl1);
        }
        if (t == T_STEPS - 1)
            *(float2*)&h_core_f[ob * C_SZ + oc] = make_float2(hv0, hv1);

        // fused mem-branch step (fast sigmoid: ~1e-7 rel err on an output)
        {
            const size_t moff = (size_t)t * N_LANES;
            hm0 = fmaf(dec, hm0, mx0);
            out_mem[moff + lm0] = hm0 * (mz0 * (1.0f / (1.0f + __expf(-mz0))));
            hm1 = fmaf(dec, hm1, mx1);
            out_mem[moff + lm1] = hm1 * (mz1 * (1.0f / (1.0f + __expf(-mz1))));
            if (t + 1 < T_STEPS) {
                const size_t noff = (size_t)(t + 1) * N_LANES;
                mx0 = xm[noff + lm0]; mz0 = zm[noff + lm0];
                mx1 = xm[noff + lm1]; mz1 = zm[noff + lm1];
            }
        }

        // prefetch pre/z for step t+1 (poll the pre-group only at boundaries)
        if (t + 1 < T_STEPS) {
            if (((t + 1) & 3) == 0) {
                const int gidx = (t + 1) >> 2;
                unsigned d;
                do { d = ld_acq(&g_pre_done[gidx]); } while (d < 12u);
            }
            const size_t nidx = (size_t)(t + 1) * B_SZ * C_SZ + (size_t)ob * C_SZ + oc;
            pre2 = __ldcg((const float2*)&g_pre[nidx]);
            z2 = *(const float2*)&zc[nidx];
        }

        // back-pressure every other step (licenses writes h(t+1) and h(t+2))
        if ((t & 1) == 0 && t >= 2 && t + 1 < T_STEPS) {
            const unsigned tgt = (unsigned)(t - 1);
            bool ok;
            do {
                unsigned f0 = ld_acq(&g_flag[lane]);
                unsigned f1 = ld_acq(&g_flag[lane + 32]);
                unsigned f2 = ld_acq(&g_flag[lane + 64]);
                ok = __all_sync(0xffffffffu,
                                f0 >= tgt && f1 >= tgt && f2 >= tgt);
            } while (!ok);
        }
    }

    h_mem_f[lm0] = hm0;
    h_mem_f[lm1] = hm1;
}

// ---------------- launch --------------------------------------------------------
extern "C" void kernel_launch(void* const* d_in, const int* in_sizes, int n_in,
                              void* d_out, int out_size) {
    const float* x_core  = (const float*)d_in[0];
    const float* z_core  = (const float*)d_in[1];
    const float* x_mem   = (const float*)d_in[2];
    const float* z_mem   = (const float*)d_in[3];
    const float* h0_core = (const float*)d_in[4];
    const float* h0_mem  = (const float*)d_in[5];
    const float* W_x     = (const float*)d_in[6];
    const float* W_h     = (const float*)d_in[7];
    const float* b_core  = (const float*)d_in[8];
    const float* a_mem   = (const float*)d_in[9];

    float* out       = (float*)d_out;
    float* out_core  = out;
    float* out_mem   = out + (size_t)T_STEPS * B_SZ * C_SZ;
    float* h_core_f  = out_mem + (size_t)T_STEPS * B_SZ * M_SZ;
    float* h_mem_f   = h_core_f + (size_t)B_SZ * C_SZ;

    cudaFuncSetAttribute(k_main, cudaFuncAttributeMaxDynamicSharedMemorySize,
                         SMEM_R);

    // reset flags + prep barrier + pre-group counters
    k_reset_bar<<<1, 128>>>();

    // fused spectral norm + fp16 conversions + h0 init
    k_prep<<<NBLK, 256>>>(W_h, W_x, x_core, h0_core);

    // combined persistent kernel: recurrence (96 blocks) + pre-GEMM (52 blocks)
    k_main<<<TOTBLK, RTHR, SMEM_R>>>(z_core, out_core, h_core_f,
                                     x_mem, z_mem, h0_mem, a_mem,
                                     out_mem, h_mem_f, b_core);
}